// round 1
// baseline (speedup 1.0000x reference)
#include <cuda_runtime.h>
#include <math.h>

#define Dn   64
#define Rn   4
#define NMAX 100000
#define EMAX 1200000
#define KT   320          // 256 (R*D relation slots) + 64 (self loop)
#define WSTR 68           // smem stride for transposed weights (x4 aligned, low conflict)
#define USTR 321          // smem stride for per-node input vectors
#define CONV_NODES 32
#define HW_NODES 32
#define HSTR 129

// ---------------- scratch (device globals: allocation-free rule) ----------------
__device__ float g_S[(size_t)NMAX * Rn * Dn];   // per-(node,rel) feature sums
__device__ int   g_cnt[NMAX * Rn];              // per-(node,rel) edge counts
__device__ float g_h1[(size_t)NMAX * Dn];
__device__ float g_g1[(size_t)NMAX * Dn];
__device__ float g_h2[(size_t)NMAX * Dn];

__device__ __forceinline__ float sigmoidf_(float v) {
    return 1.0f / (1.0f + __expf(-v));
}

// ---------------- zero the accumulators ----------------
__global__ void zero_kernel(int segs) {
    int idx = blockIdx.x * blockDim.x + threadIdx.x;
    int total4 = segs * (Dn / 4);
    if (idx < total4) reinterpret_cast<float4*>(g_S)[idx] = make_float4(0.f, 0.f, 0.f, 0.f);
    if (idx < segs) g_cnt[idx] = 0;
}

// ---------------- edge scatter: S[dst*R+rel] += x[src], cnt++ ----------------
// 16 threads per edge, float4 per thread, vectorized red (sm_90+).
__global__ void edge_kernel(const float* __restrict__ x,
                            const int* __restrict__ src,
                            const int* __restrict__ dst,
                            const int* __restrict__ rel,
                            int E) {
    int idx = blockIdx.x * blockDim.x + threadIdx.x;
    int e = idx >> 4;
    if (e >= E) return;
    int lane = idx & 15;
    int s = __ldg(src + e);
    int d = __ldg(dst + e);
    int r = __ldg(rel + e);
    int seg = d * Rn + r;
    float4 v = *reinterpret_cast<const float4*>(x + (size_t)s * Dn + lane * 4);
    float* p = g_S + (size_t)seg * Dn + lane * 4;
    asm volatile("red.global.add.v4.f32 [%0], {%1,%2,%3,%4};"
                 :: "l"(p), "f"(v.x), "f"(v.y), "f"(v.z), "f"(v.w) : "memory");
    if (lane == 0) atomicAdd(&g_cnt[seg], 1);
}

// ---------------- fused conv node: mean + [320]->64 GEMV + bias + sigmoid ----------------
// block: 256 threads, 32 nodes. smem: wT[320][68] + u[32][321] + bias[64].
__global__ void __launch_bounds__(256)
conv_node_kernel(const float* __restrict__ xin,
                 const float* __restrict__ w,   // [64][256]
                 const float* __restrict__ b,   // [64]
                 const float* __restrict__ ws,  // [64][64]
                 const float* __restrict__ bs,  // [64]
                 float* __restrict__ out,
                 int nnodes) {
    extern __shared__ float sm[];
    float* sw = sm;                       // KT * WSTR
    float* su = sm + KT * WSTR;           // CONV_NODES * USTR
    float* sb = su + CONV_NODES * USTR;   // 64
    int tid = threadIdx.x;

    // load weights transposed: sw[k][j] = w[j][k], rows 256..319 = ws
    for (int idx = tid; idx < Dn * 256; idx += 256) {
        int j = idx >> 8, k = idx & 255;
        sw[k * WSTR + j] = w[idx];
    }
    for (int idx = tid; idx < Dn * Dn; idx += 256) {
        int j = idx >> 6, k = idx & 63;
        sw[(256 + k) * WSTR + j] = ws[idx];
    }
    if (tid < Dn) sb[tid] = b[tid] + bs[tid];

    int base = blockIdx.x * CONV_NODES;
    // load per-node vectors: u = [mean(S per rel) | x]
    for (int idx = tid; idx < CONV_NODES * KT; idx += 256) {
        int n = idx / KT, k = idx - n * KT;
        int node = base + n;
        float v = 0.f;
        if (node < nnodes) {
            if (k < 256) {
                int r = k >> 6, kk = k & 63;
                int seg = node * Rn + r;
                int c = g_cnt[seg];
                c = c > 1 ? c : 1;
                v = g_S[(size_t)seg * Dn + kk] * (1.0f / (float)c);
            } else {
                v = xin[(size_t)node * Dn + (k - 256)];
            }
        }
        su[n * USTR + k] = v;
    }
    __syncthreads();

    int jq = tid & 15;   // j = jq*4 + m
    int nq = tid >> 4;   // nodes nq, nq+16
    float acc0[4] = {0.f, 0.f, 0.f, 0.f};
    float acc1[4] = {0.f, 0.f, 0.f, 0.f};
    const float* u0 = su + nq * USTR;
    const float* u1 = su + (nq + 16) * USTR;
#pragma unroll 8
    for (int k = 0; k < KT; k++) {
        float4 wv = *reinterpret_cast<const float4*>(sw + k * WSTR + jq * 4);
        float a = u0[k], c = u1[k];
        acc0[0] += a * wv.x; acc0[1] += a * wv.y; acc0[2] += a * wv.z; acc0[3] += a * wv.w;
        acc1[0] += c * wv.x; acc1[1] += c * wv.y; acc1[2] += c * wv.z; acc1[3] += c * wv.w;
    }
    int n0 = base + nq, n1 = base + nq + 16;
#pragma unroll
    for (int m = 0; m < 4; m++) {
        int j = jq * 4 + m;
        float bias = sb[j];
        if (n0 < nnodes) out[(size_t)n0 * Dn + j] = sigmoidf_(acc0[m] + bias);
        if (n1 < nnodes) out[(size_t)n1 * Dn + j] = sigmoidf_(acc1[m] + bias);
    }
}

// ---------------- fused highway: two [128]->64 GEMVs + gate blend ----------------
__global__ void __launch_bounds__(256)
highway_kernel(const float* __restrict__ h,
               const float* __restrict__ prev,
               const float* __restrict__ pw,   // [64][128]
               const float* __restrict__ pb,
               const float* __restrict__ tw,   // [64][128]
               const float* __restrict__ tb,
               float* __restrict__ out,
               int nnodes) {
    extern __shared__ float sm[];
    float* spw = sm;                         // 128 * WSTR
    float* stw = spw + 128 * WSTR;           // 128 * WSTR
    float* sc  = stw + 128 * WSTR;           // HW_NODES * HSTR
    float* sbp = sc + HW_NODES * HSTR;       // 64
    float* sbt = sbp + 64;                   // 64
    int tid = threadIdx.x;

    for (int idx = tid; idx < Dn * 128; idx += 256) {
        int j = idx >> 7, k = idx & 127;
        spw[k * WSTR + j] = pw[idx];
        stw[k * WSTR + j] = tw[idx];
    }
    if (tid < Dn) { sbp[tid] = pb[tid]; sbt[tid] = tb[tid]; }

    int base = blockIdx.x * HW_NODES;
    for (int idx = tid; idx < HW_NODES * 128; idx += 256) {
        int n = idx >> 7, k = idx & 127;
        int node = base + n;
        float v = 0.f;
        if (node < nnodes)
            v = (k < 64) ? h[(size_t)node * Dn + k] : prev[(size_t)node * Dn + (k - 64)];
        sc[n * HSTR + k] = v;
    }
    __syncthreads();

    int jq = tid & 15;
    int nq = tid >> 4;
    float ap0[4] = {0.f,0.f,0.f,0.f}, ap1[4] = {0.f,0.f,0.f,0.f};
    float ag0[4] = {0.f,0.f,0.f,0.f}, ag1[4] = {0.f,0.f,0.f,0.f};
    const float* c0 = sc + nq * HSTR;
    const float* c1 = sc + (nq + 16) * HSTR;
#pragma unroll 8
    for (int k = 0; k < 128; k++) {
        float4 pv = *reinterpret_cast<const float4*>(spw + k * WSTR + jq * 4);
        float4 tv = *reinterpret_cast<const float4*>(stw + k * WSTR + jq * 4);
        float a = c0[k], c = c1[k];
        ap0[0] += a * pv.x; ap0[1] += a * pv.y; ap0[2] += a * pv.z; ap0[3] += a * pv.w;
        ag0[0] += a * tv.x; ag0[1] += a * tv.y; ag0[2] += a * tv.z; ag0[3] += a * tv.w;
        ap1[0] += c * pv.x; ap1[1] += c * pv.y; ap1[2] += c * pv.z; ap1[3] += c * pv.w;
        ag1[0] += c * tv.x; ag1[1] += c * tv.y; ag1[2] += c * tv.z; ag1[3] += c * tv.w;
    }
    int n0 = base + nq, n1 = base + nq + 16;
#pragma unroll
    for (int m = 0; m < 4; m++) {
        int j = jq * 4 + m;
        float bp = sbp[j], bt = sbt[j];
        if (n0 < nnodes) {
            float pr = fmaxf(ap0[m] + bp, 0.f);
            float g  = sigmoidf_(ag0[m] + bt);
            float hv = h[(size_t)n0 * Dn + j];
            out[(size_t)n0 * Dn + j] = g * pr + (1.f - g) * hv;
        }
        if (n1 < nnodes) {
            float pr = fmaxf(ap1[m] + bp, 0.f);
            float g  = sigmoidf_(ag1[m] + bt);
            float hv = h[(size_t)n1 * Dn + j];
            out[(size_t)n1 * Dn + j] = g * pr + (1.f - g) * hv;
        }
    }
}

// ---------------- launch ----------------
extern "C" void kernel_launch(void* const* d_in, const int* in_sizes, int n_in,
                              void* d_out, int out_size) {
    const float* x    = (const float*)d_in[0];
    const int*   src  = (const int*)d_in[1];
    const int*   dst  = (const int*)d_in[2];
    const int*   rel  = (const int*)d_in[3];
    const float* c1w  = (const float*)d_in[4];
    const float* c1b  = (const float*)d_in[5];
    const float* c1ws = (const float*)d_in[6];
    const float* c1bs = (const float*)d_in[7];
    const float* h1pw = (const float*)d_in[8];
    const float* h1pb = (const float*)d_in[9];
    const float* h1tw = (const float*)d_in[10];
    const float* h1tb = (const float*)d_in[11];
    const float* c2w  = (const float*)d_in[12];
    const float* c2b  = (const float*)d_in[13];
    const float* c2ws = (const float*)d_in[14];
    const float* c2bs = (const float*)d_in[15];
    const float* h2pw = (const float*)d_in[16];
    const float* h2pb = (const float*)d_in[17];
    const float* h2tw = (const float*)d_in[18];
    const float* h2tb = (const float*)d_in[19];
    float* out = (float*)d_out;

    int N = in_sizes[0] / Dn;
    int E = in_sizes[1];
    int segs = N * Rn;

    float *h1p, *g1p, *h2p;
    cudaGetSymbolAddress((void**)&h1p, g_h1);
    cudaGetSymbolAddress((void**)&g1p, g_g1);
    cudaGetSymbolAddress((void**)&h2p, g_h2);

    const int convSmem = (KT * WSTR + CONV_NODES * USTR + 64) * sizeof(float);
    const int hwSmem   = (2 * 128 * WSTR + HW_NODES * HSTR + 128) * sizeof(float);
    cudaFuncSetAttribute(conv_node_kernel, cudaFuncAttributeMaxDynamicSharedMemorySize, convSmem);
    cudaFuncSetAttribute(highway_kernel,  cudaFuncAttributeMaxDynamicSharedMemorySize, hwSmem);

    int zeroGrid = (segs * (Dn / 4) + 255) / 256;
    int edgeGrid = (E * 16 + 255) / 256;
    int nodeGrid = (N + CONV_NODES - 1) / CONV_NODES;

    // ---- layer 1 ----
    zero_kernel<<<zeroGrid, 256>>>(segs);
    edge_kernel<<<edgeGrid, 256>>>(x, src, dst, rel, E);
    conv_node_kernel<<<nodeGrid, 256, convSmem>>>(x, c1w, c1b, c1ws, c1bs, h1p, N);
    highway_kernel<<<nodeGrid, 256, hwSmem>>>(h1p, x, h1pw, h1pb, h1tw, h1tb, g1p, N);

    // ---- layer 2 ----
    zero_kernel<<<zeroGrid, 256>>>(segs);
    edge_kernel<<<edgeGrid, 256>>>(g1p, src, dst, rel, E);
    conv_node_kernel<<<nodeGrid, 256, convSmem>>>(g1p, c2w, c2b, c2ws, c2bs, h2p, N);
    highway_kernel<<<nodeGrid, 256, hwSmem>>>(h2p, h1p, h2pw, h2pb, h2tw, h2tb, out, N);
}

// round 2
// speedup vs baseline: 1.4284x; 1.4284x over previous
#include <cuda_runtime.h>
#include <math.h>

#define Dn   64
#define Rn   4
#define NMAX 100000
#define KT   320          // 256 (R*D relation slots) + 64 (self loop)
#define SEGS (NMAX * Rn)
#define SROW (Rn * Dn)    // 256 floats per node in S
#define USTR 324          // su node-major stride (320 + pad, /4 aligned)
#define CSTR 132          // highway concat stride (128 + pad)
#define NODES_PB 64       // nodes per block (conv & highway)

// ---------------- scratch (device globals: allocation-free rule) ----------------
__device__ float g_S[2][(size_t)NMAX * SROW];   // double-buffered per-(node,rel) sums
__device__ int   g_cnt[SEGS];                   // per-(node,rel) edge counts (same both layers)
__device__ float g_h1[(size_t)NMAX * Dn];
__device__ float g_g1[(size_t)NMAX * Dn];
__device__ float g_h2[(size_t)NMAX * Dn];

__device__ __forceinline__ float sigmoidf_(float v) {
    return 1.0f / (1.0f + __expf(-v));
}

// ---------------- zero both S buffers + counts in one pass ----------------
__global__ void zero_kernel() {
    size_t idx = (size_t)blockIdx.x * blockDim.x + threadIdx.x;
    size_t total4 = (size_t)2 * NMAX * SROW / 4;
    if (idx < total4)
        reinterpret_cast<float4*>(g_S)[idx] = make_float4(0.f, 0.f, 0.f, 0.f);
    if (idx < SEGS) g_cnt[idx] = 0;
}

// ---------------- edge scatter: S[dst*R+rel] += x[src], cnt++ (pass 1 only) ----------------
__global__ void edge_kernel(const float* __restrict__ x,
                            const int* __restrict__ src,
                            const int* __restrict__ dst,
                            const int* __restrict__ rel,
                            float* __restrict__ Sbuf,
                            int E, int do_count) {
    int idx = blockIdx.x * blockDim.x + threadIdx.x;
    int e = idx >> 4;
    if (e >= E) return;
    int lane = idx & 15;
    int s = __ldg(src + e);
    int d = __ldg(dst + e);
    int r = __ldg(rel + e);
    int seg = d * Rn + r;
    float4 v = *reinterpret_cast<const float4*>(x + (size_t)s * Dn + lane * 4);
    float* p = Sbuf + (size_t)seg * Dn + lane * 4;
    asm volatile("red.global.add.v4.f32 [%0], {%1,%2,%3,%4};"
                 :: "l"(p), "f"(v.x), "f"(v.y), "f"(v.z), "f"(v.w) : "memory");
    if (do_count && lane == 0) atomicAdd(&g_cnt[seg], 1);
}

// ---------------- fused conv: mean + [320]->64 GEMM tile + bias + sigmoid ----------------
// 64 nodes/block, 256 threads, 4 nodes x 4 outputs per thread.
__global__ void __launch_bounds__(256)
conv_node_kernel(const float* __restrict__ xin,
                 const float* __restrict__ Sbuf,
                 const float* __restrict__ w,   // [64][256]
                 const float* __restrict__ b,
                 const float* __restrict__ ws,  // [64][64]
                 const float* __restrict__ bs,
                 float* __restrict__ out,
                 int nnodes) {
    extern __shared__ float sm[];
    float* sw = sm;                         // KT * 64 (k-major, sw[k*64 + j])
    float* su = sm + KT * Dn;               // NODES_PB * USTR (node-major)
    float* sb = su + NODES_PB * USTR;       // 64
    int tid = threadIdx.x;

    // stage weights transposed: sw[k][j]; rows 256..319 = self-loop ws
    for (int idx = tid; idx < Dn * 256; idx += 256) {
        int j = idx >> 8, k = idx & 255;
        sw[k * Dn + j] = w[idx];
    }
    for (int idx = tid; idx < Dn * Dn; idx += 256) {
        int j = idx >> 6, k = idx & 63;
        sw[(256 + k) * Dn + j] = ws[idx];
    }
    if (tid < Dn) sb[tid] = b[tid] + bs[tid];

    int base = blockIdx.x * NODES_PB;
    // stage per-node vectors u = [S/cnt (256) | x (64)], float4 chunks
    for (int idx = tid; idx < NODES_PB * (KT / 4); idx += 256) {
        int n = idx / (KT / 4), kq = idx - n * (KT / 4);
        int node = base + n;
        float4 v = make_float4(0.f, 0.f, 0.f, 0.f);
        if (node < nnodes) {
            if (kq < 64) {
                int r = kq >> 4;
                int c = __ldg(&g_cnt[node * Rn + r]);
                float inv = 1.0f / (float)(c > 1 ? c : 1);
                v = *reinterpret_cast<const float4*>(Sbuf + (size_t)node * SROW + kq * 4);
                v.x *= inv; v.y *= inv; v.z *= inv; v.w *= inv;
            } else {
                v = *reinterpret_cast<const float4*>(xin + (size_t)node * Dn + (kq - 64) * 4);
            }
        }
        *reinterpret_cast<float4*>(su + n * USTR + kq * 4) = v;
    }
    __syncthreads();

    int jq = tid & 15;   // output cols jq*4 .. +3
    int nq = tid >> 4;   // nodes nq*4 .. +3
    float acc[4][4];
#pragma unroll
    for (int i = 0; i < 4; i++)
#pragma unroll
        for (int m = 0; m < 4; m++) acc[i][m] = 0.f;

    const float* u0 = su + (nq * 4 + 0) * USTR;
    const float* u1 = su + (nq * 4 + 1) * USTR;
    const float* u2 = su + (nq * 4 + 2) * USTR;
    const float* u3 = su + (nq * 4 + 3) * USTR;
    const float* wp = sw + jq * 4;
#pragma unroll 4
    for (int k = 0; k < KT; k++) {
        float4 wv = *reinterpret_cast<const float4*>(wp + k * Dn);
        float a0 = u0[k], a1 = u1[k], a2 = u2[k], a3 = u3[k];
        acc[0][0] += a0 * wv.x; acc[0][1] += a0 * wv.y; acc[0][2] += a0 * wv.z; acc[0][3] += a0 * wv.w;
        acc[1][0] += a1 * wv.x; acc[1][1] += a1 * wv.y; acc[1][2] += a1 * wv.z; acc[1][3] += a1 * wv.w;
        acc[2][0] += a2 * wv.x; acc[2][1] += a2 * wv.y; acc[2][2] += a2 * wv.z; acc[2][3] += a2 * wv.w;
        acc[3][0] += a3 * wv.x; acc[3][1] += a3 * wv.y; acc[3][2] += a3 * wv.z; acc[3][3] += a3 * wv.w;
    }

    float b0 = sb[jq * 4 + 0], b1 = sb[jq * 4 + 1], b2 = sb[jq * 4 + 2], b3 = sb[jq * 4 + 3];
#pragma unroll
    for (int i = 0; i < 4; i++) {
        int node = base + nq * 4 + i;
        if (node < nnodes) {
            float4 o;
            o.x = sigmoidf_(acc[i][0] + b0);
            o.y = sigmoidf_(acc[i][1] + b1);
            o.z = sigmoidf_(acc[i][2] + b2);
            o.w = sigmoidf_(acc[i][3] + b3);
            *reinterpret_cast<float4*>(out + (size_t)node * Dn + jq * 4) = o;
        }
    }
}

// ---------------- fused highway: two [128]->64 GEMM tiles + gate blend ----------------
__global__ void __launch_bounds__(256)
highway_kernel(const float* __restrict__ h,
               const float* __restrict__ prev,
               const float* __restrict__ pw,   // [64][128]
               const float* __restrict__ pb,
               const float* __restrict__ tw,   // [64][128]
               const float* __restrict__ tb,
               float* __restrict__ out,
               int nnodes) {
    extern __shared__ float sm[];
    float* spw = sm;                         // 128 * 64
    float* stw = spw + 128 * Dn;             // 128 * 64
    float* sc  = stw + 128 * Dn;             // NODES_PB * CSTR
    float* sbp = sc + NODES_PB * CSTR;       // 64
    float* sbt = sbp + Dn;                   // 64
    int tid = threadIdx.x;

    for (int idx = tid; idx < Dn * 128; idx += 256) {
        int j = idx >> 7, k = idx & 127;
        spw[k * Dn + j] = pw[idx];
        stw[k * Dn + j] = tw[idx];
    }
    if (tid < Dn) { sbp[tid] = pb[tid]; sbt[tid] = tb[tid]; }

    int base = blockIdx.x * NODES_PB;
    for (int idx = tid; idx < NODES_PB * 32; idx += 256) {
        int n = idx >> 5, kq = idx & 31;
        int node = base + n;
        float4 v = make_float4(0.f, 0.f, 0.f, 0.f);
        if (node < nnodes)
            v = (kq < 16)
                ? *reinterpret_cast<const float4*>(h + (size_t)node * Dn + kq * 4)
                : *reinterpret_cast<const float4*>(prev + (size_t)node * Dn + (kq - 16) * 4);
        *reinterpret_cast<float4*>(sc + n * CSTR + kq * 4) = v;
    }
    __syncthreads();

    int jq = tid & 15;
    int nq = tid >> 4;
    float ap[4][4], ag[4][4];
#pragma unroll
    for (int i = 0; i < 4; i++)
#pragma unroll
        for (int m = 0; m < 4; m++) { ap[i][m] = 0.f; ag[i][m] = 0.f; }

    const float* c0 = sc + (nq * 4 + 0) * CSTR;
    const float* c1 = sc + (nq * 4 + 1) * CSTR;
    const float* c2 = sc + (nq * 4 + 2) * CSTR;
    const float* c3 = sc + (nq * 4 + 3) * CSTR;
    const float* pwp = spw + jq * 4;
    const float* twp = stw + jq * 4;
#pragma unroll 2
    for (int k = 0; k < 128; k++) {
        float4 pv = *reinterpret_cast<const float4*>(pwp + k * Dn);
        float4 tv = *reinterpret_cast<const float4*>(twp + k * Dn);
        float a0 = c0[k], a1 = c1[k], a2 = c2[k], a3 = c3[k];
        ap[0][0] += a0 * pv.x; ap[0][1] += a0 * pv.y; ap[0][2] += a0 * pv.z; ap[0][3] += a0 * pv.w;
        ag[0][0] += a0 * tv.x; ag[0][1] += a0 * tv.y; ag[0][2] += a0 * tv.z; ag[0][3] += a0 * tv.w;
        ap[1][0] += a1 * pv.x; ap[1][1] += a1 * pv.y; ap[1][2] += a1 * pv.z; ap[1][3] += a1 * pv.w;
        ag[1][0] += a1 * tv.x; ag[1][1] += a1 * tv.y; ag[1][2] += a1 * tv.z; ag[1][3] += a1 * tv.w;
        ap[2][0] += a2 * pv.x; ap[2][1] += a2 * pv.y; ap[2][2] += a2 * pv.z; ap[2][3] += a2 * pv.w;
        ag[2][0] += a2 * tv.x; ag[2][1] += a2 * tv.y; ag[2][2] += a2 * tv.z; ag[2][3] += a2 * tv.w;
        ap[3][0] += a3 * pv.x; ap[3][1] += a3 * pv.y; ap[3][2] += a3 * pv.z; ap[3][3] += a3 * pv.w;
        ag[3][0] += a3 * tv.x; ag[3][1] += a3 * tv.y; ag[3][2] += a3 * tv.z; ag[3][3] += a3 * tv.w;
    }

    float bp0 = sbp[jq * 4 + 0], bp1 = sbp[jq * 4 + 1], bp2 = sbp[jq * 4 + 2], bp3 = sbp[jq * 4 + 3];
    float bt0 = sbt[jq * 4 + 0], bt1 = sbt[jq * 4 + 1], bt2 = sbt[jq * 4 + 2], bt3 = sbt[jq * 4 + 3];
#pragma unroll
    for (int i = 0; i < 4; i++) {
        int node = base + nq * 4 + i;
        if (node < nnodes) {
            float4 hv = *reinterpret_cast<const float4*>(h + (size_t)node * Dn + jq * 4);
            float4 o;
            {
                float pr = fmaxf(ap[i][0] + bp0, 0.f);
                float g  = sigmoidf_(ag[i][0] + bt0);
                o.x = g * pr + (1.f - g) * hv.x;
            }
            {
                float pr = fmaxf(ap[i][1] + bp1, 0.f);
                float g  = sigmoidf_(ag[i][1] + bt1);
                o.y = g * pr + (1.f - g) * hv.y;
            }
            {
                float pr = fmaxf(ap[i][2] + bp2, 0.f);
                float g  = sigmoidf_(ag[i][2] + bt2);
                o.z = g * pr + (1.f - g) * hv.z;
            }
            {
                float pr = fmaxf(ap[i][3] + bp3, 0.f);
                float g  = sigmoidf_(ag[i][3] + bt3);
                o.w = g * pr + (1.f - g) * hv.w;
            }
            *reinterpret_cast<float4*>(out + (size_t)node * Dn + jq * 4) = o;
        }
    }
}

// ---------------- launch ----------------
extern "C" void kernel_launch(void* const* d_in, const int* in_sizes, int n_in,
                              void* d_out, int out_size) {
    const float* x    = (const float*)d_in[0];
    const int*   src  = (const int*)d_in[1];
    const int*   dst  = (const int*)d_in[2];
    const int*   rel  = (const int*)d_in[3];
    const float* c1w  = (const float*)d_in[4];
    const float* c1b  = (const float*)d_in[5];
    const float* c1ws = (const float*)d_in[6];
    const float* c1bs = (const float*)d_in[7];
    const float* h1pw = (const float*)d_in[8];
    const float* h1pb = (const float*)d_in[9];
    const float* h1tw = (const float*)d_in[10];
    const float* h1tb = (const float*)d_in[11];
    const float* c2w  = (const float*)d_in[12];
    const float* c2b  = (const float*)d_in[13];
    const float* c2ws = (const float*)d_in[14];
    const float* c2bs = (const float*)d_in[15];
    const float* h2pw = (const float*)d_in[16];
    const float* h2pb = (const float*)d_in[17];
    const float* h2tw = (const float*)d_in[18];
    const float* h2tb = (const float*)d_in[19];
    float* out = (float*)d_out;

    int N = in_sizes[0] / Dn;
    int E = in_sizes[1];

    float *Sp, *h1p, *g1p, *h2p;
    cudaGetSymbolAddress((void**)&Sp, g_S);
    cudaGetSymbolAddress((void**)&h1p, g_h1);
    cudaGetSymbolAddress((void**)&g1p, g_g1);
    cudaGetSymbolAddress((void**)&h2p, g_h2);
    float* S0 = Sp;
    float* S1 = Sp + (size_t)NMAX * SROW;

    const int convSmem = (KT * Dn + NODES_PB * USTR + 64) * sizeof(float);
    const int hwSmem   = (2 * 128 * Dn + NODES_PB * CSTR + 128) * sizeof(float);
    cudaFuncSetAttribute(conv_node_kernel, cudaFuncAttributeMaxDynamicSharedMemorySize, convSmem);
    cudaFuncSetAttribute(highway_kernel,  cudaFuncAttributeMaxDynamicSharedMemorySize, hwSmem);

    size_t zeroItems = (size_t)2 * NMAX * SROW / 4;
    int zeroGrid = (int)((zeroItems + 255) / 256);
    int edgeGrid = (E * 16 + 255) / 256;
    int nodeGrid = (N + NODES_PB - 1) / NODES_PB;

    zero_kernel<<<zeroGrid, 256>>>();

    // ---- layer 1 ----
    edge_kernel<<<edgeGrid, 256>>>(x, src, dst, rel, S0, E, 1);
    conv_node_kernel<<<nodeGrid, 256, convSmem>>>(x, S0, c1w, c1b, c1ws, c1bs, h1p, N);
    highway_kernel<<<nodeGrid, 256, hwSmem>>>(h1p, x, h1pw, h1pb, h1tw, h1tb, g1p, N);

    // ---- layer 2 ----
    edge_kernel<<<edgeGrid, 256>>>(g1p, src, dst, rel, S1, E, 0);
    conv_node_kernel<<<nodeGrid, 256, convSmem>>>(g1p, S1, c2w, c2b, c2ws, c2bs, h2p, N);
    highway_kernel<<<nodeGrid, 256, hwSmem>>>(h2p, h1p, h2pw, h2pb, h2tw, h2tb, out, N);
}

// round 4
// speedup vs baseline: 1.9927x; 1.3951x over previous
#include <cuda_runtime.h>
#include <math.h>

#define Dn   64
#define Rn   4
#define NMAX 100000
#define EMAX 1200000
#define SEGS (NMAX * Rn)
#define KT   320          // 256 relation slots + 64 self-loop
#define WSTR 68           // weight smem stride (16B-aligned)
#define CUSTR 324         // conv node-vector stride (320 + 4 pad, float4-aligned)
#define CNPB 64           // conv nodes per block
#define HUSTR 132         // highway concat stride (128 + 4 pad)
#define HNPB 128          // highway nodes per block

// ---------------- scratch ----------------
__device__ int   g_deg[SEGS];
__device__ int   g_off[SEGS + 1];
__device__ int   g_cur[SEGS];
__device__ int   g_srcs[EMAX];
__device__ int   g_part[512];
__device__ float g_S[(size_t)SEGS * Dn];
__device__ float g_h1[(size_t)NMAX * Dn];
__device__ float g_g1[(size_t)NMAX * Dn];
__device__ float g_h2[(size_t)NMAX * Dn];

__device__ __forceinline__ float sigmoidf_(float v) {
    return 1.0f / (1.0f + __expf(-v));
}

// ---------------- CSR build ----------------
__global__ void zero_deg_kernel() {
    int i = blockIdx.x * blockDim.x + threadIdx.x;
    if (i < SEGS) g_deg[i] = 0;
}

__global__ void hist_kernel(const int* __restrict__ dst, const int* __restrict__ rel, int E) {
    int e = blockIdx.x * blockDim.x + threadIdx.x;
    if (e < E) atomicAdd(&g_deg[dst[e] * Rn + rel[e]], 1);
}

__global__ void __launch_bounds__(1024) scan1_kernel(int n) {
    __shared__ int wsum[32];
    int i = blockIdx.x * 1024 + threadIdx.x;
    int lane = threadIdx.x & 31, wid = threadIdx.x >> 5;
    int v = (i < n) ? g_deg[i] : 0;
    int s = v;
#pragma unroll
    for (int d = 1; d < 32; d <<= 1) {
        int t = __shfl_up_sync(0xffffffffu, s, d);
        if (lane >= d) s += t;
    }
    if (lane == 31) wsum[wid] = s;
    __syncthreads();
    if (wid == 0) {
        int t = wsum[lane];
#pragma unroll
        for (int d = 1; d < 32; d <<= 1) {
            int u = __shfl_up_sync(0xffffffffu, t, d);
            if (lane >= d) t += u;
        }
        wsum[lane] = t;
    }
    __syncthreads();
    int add = (wid > 0) ? wsum[wid - 1] : 0;
    int inc = s + add;
    if (i < n) g_off[i] = inc - v;
    if (threadIdx.x == 1023) g_part[blockIdx.x] = inc;
}

__global__ void __launch_bounds__(512) scan2_kernel(int n) {
    __shared__ int wsum[16];
    int i = threadIdx.x;
    int lane = i & 31, wid = i >> 5;
    int v = (i < n) ? g_part[i] : 0;
    int s = v;
#pragma unroll
    for (int d = 1; d < 32; d <<= 1) {
        int t = __shfl_up_sync(0xffffffffu, s, d);
        if (lane >= d) s += t;
    }
    if (lane == 31) wsum[wid] = s;
    __syncthreads();
    if (wid == 0 && lane < 16) {
        int t = wsum[lane];
#pragma unroll
        for (int d = 1; d < 16; d <<= 1) {
            int u = __shfl_up_sync(0x0000ffffu, t, d);
            if (lane >= d) t += u;
        }
        wsum[lane] = t;
    }
    __syncthreads();
    int add = (wid > 0) ? wsum[wid - 1] : 0;
    if (i < n) g_part[i] = s - v + add;
}

__global__ void scan3_kernel(int n, int E) {
    int i = blockIdx.x * blockDim.x + threadIdx.x;
    if (i < n) {
        int o = g_off[i] + g_part[i >> 10];
        g_off[i] = o;
        g_cur[i] = o;
    }
    if (i == 0) g_off[n] = E;
}

__global__ void scatter_kernel(const int* __restrict__ src, const int* __restrict__ dst,
                               const int* __restrict__ rel, int E) {
    int e = blockIdx.x * blockDim.x + threadIdx.x;
    if (e >= E) return;
    int seg = dst[e] * Rn + rel[e];
    int p = atomicAdd(&g_cur[seg], 1);
    g_srcs[p] = src[e];
}

// ---------------- aggregate: S[seg] = sum over edges of x[src] ----------------
__global__ void __launch_bounds__(256) aggregate_kernel(const float* __restrict__ x) {
    int t = blockIdx.x * 256 + threadIdx.x;
    int seg = t >> 4;
    int lane = t & 15;
    if (seg >= SEGS) return;
    int e0 = __ldg(&g_off[seg]);
    int e1 = __ldg(&g_off[seg + 1]);
    float4 acc = make_float4(0.f, 0.f, 0.f, 0.f);
    for (int e = e0; e < e1; e++) {
        int s = __ldg(&g_srcs[e]);
        float4 v = *reinterpret_cast<const float4*>(x + (size_t)s * Dn + lane * 4);
        acc.x += v.x; acc.y += v.y; acc.z += v.z; acc.w += v.w;
    }
    *reinterpret_cast<float4*>(g_S + (size_t)seg * Dn + lane * 4) = acc;
}

// ---------------- fused conv: mean + [320]->64 GEMM + bias + sigmoid ----------------
// 512 threads, 64 nodes/block. warp -> 8 output cols (broadcast weight reads),
// thread -> 1 node x 8 outputs.
__global__ void __launch_bounds__(512)
conv_node_kernel(const float* __restrict__ xin,
                 const float* __restrict__ w,   // [64][256]
                 const float* __restrict__ b,
                 const float* __restrict__ ws,  // [64][64]
                 const float* __restrict__ bs,
                 float* __restrict__ out,
                 int nnodes) {
    extern __shared__ float sm[];
    float* sw = sm;                       // KT * WSTR = 21760
    float* su = sm + KT * WSTR;           // CNPB * CUSTR = 20736
    float* sb = su + CNPB * CUSTR;        // 64
    int tid = threadIdx.x;
    int lane = tid & 31, warpid = tid >> 5;
    int og = warpid >> 1;                 // output cols og*8 .. +7
    int half = warpid & 1;                // node half (0..31 / 32..63)

    // stage weights transposed: sw[k][j]
    for (int idx = tid; idx < Dn * 256; idx += 512) {
        int j = idx >> 8, k = idx & 255;
        sw[k * WSTR + j] = w[idx];
    }
    for (int idx = tid; idx < Dn * Dn; idx += 512) {
        int j = idx >> 6, k = idx & 63;
        sw[(256 + k) * WSTR + j] = ws[idx];
    }
    if (tid < Dn) sb[tid] = b[tid] + bs[tid];

    int base = blockIdx.x * CNPB;
    // stage node vectors u = [S/deg (256) | x (64)], float4 chunks (80 per node)
    for (int idx = tid; idx < CNPB * (KT / 4); idx += 512) {
        int n = idx / (KT / 4), kq = idx - n * (KT / 4);
        int node = base + n;
        float4 v = make_float4(0.f, 0.f, 0.f, 0.f);
        if (node < nnodes) {
            if (kq < 64) {
                int r = kq >> 4;
                int d = __ldg(&g_deg[node * Rn + r]);
                float inv = 1.0f / (float)(d > 1 ? d : 1);
                v = *reinterpret_cast<const float4*>(g_S + (size_t)node * 256 + kq * 4);
                v.x *= inv; v.y *= inv; v.z *= inv; v.w *= inv;
            } else {
                v = *reinterpret_cast<const float4*>(xin + (size_t)node * Dn + (kq - 64) * 4);
            }
        }
        *reinterpret_cast<float4*>(su + n * CUSTR + kq * 4) = v;
    }
    __syncthreads();

    int n0 = half * 32 + lane;          // 0..63
    float acc[8];
#pragma unroll
    for (int m = 0; m < 8; m++) acc[m] = 0.f;

    const float* u = su + n0 * CUSTR;
    const float* wp = sw + og * 8;
#pragma unroll 4
    for (int k4 = 0; k4 < KT / 4; k4++) {
        float a[4];
        *reinterpret_cast<float4*>(a) = *reinterpret_cast<const float4*>(u + k4 * 4);
#pragma unroll
        for (int i = 0; i < 4; i++) {
            int k = k4 * 4 + i;
            float4 w0 = *reinterpret_cast<const float4*>(wp + k * WSTR);
            float4 w1 = *reinterpret_cast<const float4*>(wp + k * WSTR + 4);
            acc[0] += a[i] * w0.x; acc[1] += a[i] * w0.y; acc[2] += a[i] * w0.z; acc[3] += a[i] * w0.w;
            acc[4] += a[i] * w1.x; acc[5] += a[i] * w1.y; acc[6] += a[i] * w1.z; acc[7] += a[i] * w1.w;
        }
    }

    int node = base + n0;
    if (node < nnodes) {
        float4 o0, o1;
        o0.x = sigmoidf_(acc[0] + sb[og * 8 + 0]); o0.y = sigmoidf_(acc[1] + sb[og * 8 + 1]);
        o0.z = sigmoidf_(acc[2] + sb[og * 8 + 2]); o0.w = sigmoidf_(acc[3] + sb[og * 8 + 3]);
        o1.x = sigmoidf_(acc[4] + sb[og * 8 + 4]); o1.y = sigmoidf_(acc[5] + sb[og * 8 + 5]);
        o1.z = sigmoidf_(acc[6] + sb[og * 8 + 6]); o1.w = sigmoidf_(acc[7] + sb[og * 8 + 7]);
        *reinterpret_cast<float4*>(out + (size_t)node * Dn + og * 8) = o0;
        *reinterpret_cast<float4*>(out + (size_t)node * Dn + og * 8 + 4) = o1;
    }
}

// ---------------- fused highway: two [128]->64 GEMMs + gate blend ----------------
// 512 threads, 128 nodes/block, thread -> 2 nodes x 8 outputs (x2 matrices).
__global__ void __launch_bounds__(512)
highway_kernel(const float* __restrict__ h,
               const float* __restrict__ prev,
               const float* __restrict__ pw,   // [64][128]
               const float* __restrict__ pb,
               const float* __restrict__ tw,   // [64][128]
               const float* __restrict__ tb,
               float* __restrict__ out,
               int nnodes) {
    extern __shared__ float sm[];
    float* spw = sm;                        // 128 * WSTR
    float* stw = spw + 128 * WSTR;          // 128 * WSTR
    float* sc  = stw + 128 * WSTR;          // HNPB * HUSTR
    float* sbp = sc + HNPB * HUSTR;         // 64
    float* sbt = sbp + Dn;                  // 64
    int tid = threadIdx.x;
    int lane = tid & 31, warpid = tid >> 5;
    int og = warpid >> 1;
    int half = warpid & 1;

    for (int idx = tid; idx < Dn * 128; idx += 512) {
        int j = idx >> 7, k = idx & 127;
        spw[k * WSTR + j] = pw[idx];
        stw[k * WSTR + j] = tw[idx];
    }
    if (tid < Dn) { sbp[tid] = pb[tid]; sbt[tid] = tb[tid]; }

    int base = blockIdx.x * HNPB;
    for (int idx = tid; idx < HNPB * 32; idx += 512) {
        int n = idx >> 5, kq = idx & 31;
        int node = base + n;
        float4 v = make_float4(0.f, 0.f, 0.f, 0.f);
        if (node < nnodes)
            v = (kq < 16)
                ? *reinterpret_cast<const float4*>(h + (size_t)node * Dn + kq * 4)
                : *reinterpret_cast<const float4*>(prev + (size_t)node * Dn + (kq - 16) * 4);
        *reinterpret_cast<float4*>(sc + n * HUSTR + kq * 4) = v;
    }
    __syncthreads();

    int n0 = half * 64 + lane;   // [0,32) or [64,96)
    int n1 = n0 + 32;            // [32,64) or [96,128)
    float ap0[8], ap1[8], ag0[8], ag1[8];
#pragma unroll
    for (int m = 0; m < 8; m++) { ap0[m] = 0.f; ap1[m] = 0.f; ag0[m] = 0.f; ag1[m] = 0.f; }

    const float* c0 = sc + n0 * HUSTR;
    const float* c1 = sc + n1 * HUSTR;
    const float* pp = spw + og * 8;
    const float* tp = stw + og * 8;
#pragma unroll 2
    for (int k4 = 0; k4 < 32; k4++) {
        float a0[4], a1[4];
        *reinterpret_cast<float4*>(a0) = *reinterpret_cast<const float4*>(c0 + k4 * 4);
        *reinterpret_cast<float4*>(a1) = *reinterpret_cast<const float4*>(c1 + k4 * 4);
#pragma unroll
        for (int i = 0; i < 4; i++) {
            int k = k4 * 4 + i;
            float4 p0 = *reinterpret_cast<const float4*>(pp + k * WSTR);
            float4 p1 = *reinterpret_cast<const float4*>(pp + k * WSTR + 4);
            float4 t0 = *reinterpret_cast<const float4*>(tp + k * WSTR);
            float4 t1 = *reinterpret_cast<const float4*>(tp + k * WSTR + 4);
            ap0[0] += a0[i] * p0.x; ap0[1] += a0[i] * p0.y; ap0[2] += a0[i] * p0.z; ap0[3] += a0[i] * p0.w;
            ap0[4] += a0[i] * p1.x; ap0[5] += a0[i] * p1.y; ap0[6] += a0[i] * p1.z; ap0[7] += a0[i] * p1.w;
            ag0[0] += a0[i] * t0.x; ag0[1] += a0[i] * t0.y; ag0[2] += a0[i] * t0.z; ag0[3] += a0[i] * t0.w;
            ag0[4] += a0[i] * t1.x; ag0[5] += a0[i] * t1.y; ag0[6] += a0[i] * t1.z; ag0[7] += a0[i] * t1.w;
            ap1[0] += a1[i] * p0.x; ap1[1] += a1[i] * p0.y; ap1[2] += a1[i] * p0.z; ap1[3] += a1[i] * p0.w;
            ap1[4] += a1[i] * p1.x; ap1[5] += a1[i] * p1.y; ap1[6] += a1[i] * p1.z; ap1[7] += a1[i] * p1.w;
            ag1[0] += a1[i] * t0.x; ag1[1] += a1[i] * t0.y; ag1[2] += a1[i] * t0.z; ag1[3] += a1[i] * t0.w;
            ag1[4] += a1[i] * t1.x; ag1[5] += a1[i] * t1.y; ag1[6] += a1[i] * t1.z; ag1[7] += a1[i] * t1.w;
        }
    }

    float bp[8], bt[8];
#pragma unroll
    for (int m = 0; m < 8; m++) { bp[m] = sbp[og * 8 + m]; bt[m] = sbt[og * 8 + m]; }

    int node0 = base + n0, node1 = base + n1;
    if (node0 < nnodes) {
        float4 hv0 = *reinterpret_cast<const float4*>(h + (size_t)node0 * Dn + og * 8);
        float4 hv1 = *reinterpret_cast<const float4*>(h + (size_t)node0 * Dn + og * 8 + 4);
        float hv[8] = {hv0.x, hv0.y, hv0.z, hv0.w, hv1.x, hv1.y, hv1.z, hv1.w};
        float o[8];
#pragma unroll
        for (int m = 0; m < 8; m++) {
            float pr = fmaxf(ap0[m] + bp[m], 0.f);
            float g  = sigmoidf_(ag0[m] + bt[m]);
            o[m] = g * pr + (1.f - g) * hv[m];
        }
        *reinterpret_cast<float4*>(out + (size_t)node0 * Dn + og * 8)     = *reinterpret_cast<float4*>(o);
        *reinterpret_cast<float4*>(out + (size_t)node0 * Dn + og * 8 + 4) = *reinterpret_cast<float4*>(o + 4);
    }
    if (node1 < nnodes) {
        float4 hv0 = *reinterpret_cast<const float4*>(h + (size_t)node1 * Dn + og * 8);
        float4 hv1 = *reinterpret_cast<const float4*>(h + (size_t)node1 * Dn + og * 8 + 4);
        float hv[8] = {hv0.x, hv0.y, hv0.z, hv0.w, hv1.x, hv1.y, hv1.z, hv1.w};
        float o[8];
#pragma unroll
        for (int m = 0; m < 8; m++) {
            float pr = fmaxf(ap1[m] + bp[m], 0.f);
            float g  = sigmoidf_(ag1[m] + bt[m]);
            o[m] = g * pr + (1.f - g) * hv[m];
        }
        *reinterpret_cast<float4*>(out + (size_t)node1 * Dn + og * 8)     = *reinterpret_cast<float4*>(o);
        *reinterpret_cast<float4*>(out + (size_t)node1 * Dn + og * 8 + 4) = *reinterpret_cast<float4*>(o + 4);
    }
}

// ---------------- launch ----------------
extern "C" void kernel_launch(void* const* d_in, const int* in_sizes, int n_in,
                              void* d_out, int out_size) {
    const float* x    = (const float*)d_in[0];
    const int*   src  = (const int*)d_in[1];
    const int*   dst  = (const int*)d_in[2];
    const int*   rel  = (const int*)d_in[3];
    const float* c1w  = (const float*)d_in[4];
    const float* c1b  = (const float*)d_in[5];
    const float* c1ws = (const float*)d_in[6];
    const float* c1bs = (const float*)d_in[7];
    const float* h1pw = (const float*)d_in[8];
    const float* h1pb = (const float*)d_in[9];
    const float* h1tw = (const float*)d_in[10];
    const float* h1tb = (const float*)d_in[11];
    const float* c2w  = (const float*)d_in[12];
    const float* c2b  = (const float*)d_in[13];
    const float* c2ws = (const float*)d_in[14];
    const float* c2bs = (const float*)d_in[15];
    const float* h2pw = (const float*)d_in[16];
    const float* h2pb = (const float*)d_in[17];
    const float* h2tw = (const float*)d_in[18];
    const float* h2tb = (const float*)d_in[19];
    float* out = (float*)d_out;

    int N = in_sizes[0] / Dn;
    int E = in_sizes[1];

    float *h1p, *g1p, *h2p;
    cudaGetSymbolAddress((void**)&h1p, g_h1);
    cudaGetSymbolAddress((void**)&g1p, g_g1);
    cudaGetSymbolAddress((void**)&h2p, g_h2);

    const int convSmem = (KT * WSTR + CNPB * CUSTR + 64) * sizeof(float);
    const int hwSmem   = (2 * 128 * WSTR + HNPB * HUSTR + 128) * sizeof(float);
    cudaFuncSetAttribute(conv_node_kernel, cudaFuncAttributeMaxDynamicSharedMemorySize, convSmem);
    cudaFuncSetAttribute(highway_kernel,  cudaFuncAttributeMaxDynamicSharedMemorySize, hwSmem);

    int convGrid = (N + CNPB - 1) / CNPB;
    int hwGrid   = (N + HNPB - 1) / HNPB;
    int scanBlocks = (SEGS + 1023) / 1024;

    // ---- CSR build (graph identical in both layers) ----
    zero_deg_kernel<<<(SEGS + 255) / 256, 256>>>();
    hist_kernel<<<(E + 255) / 256, 256>>>(dst, rel, E);
    scan1_kernel<<<scanBlocks, 1024>>>(SEGS);
    scan2_kernel<<<1, 512>>>(scanBlocks);
    scan3_kernel<<<(SEGS + 255) / 256, 256>>>(SEGS, E);
    scatter_kernel<<<(E + 255) / 256, 256>>>(src, dst, rel, E);

    int aggGrid = SEGS / 16;

    // ---- layer 1 ----
    aggregate_kernel<<<aggGrid, 256>>>(x);
    conv_node_kernel<<<convGrid, 512, convSmem>>>(x, c1w, c1b, c1ws, c1bs, h1p, N);
    highway_kernel<<<hwGrid, 512, hwSmem>>>(h1p, x, h1pw, h1pb, h1tw, h1tb, g1p, N);

    // ---- layer 2 ----
    aggregate_kernel<<<aggGrid, 256>>>(g1p);
    conv_node_kernel<<<convGrid, 512, convSmem>>>(g1p, c2w, c2b, c2ws, c2bs, h2p, N);
    highway_kernel<<<hwGrid, 512, hwSmem>>>(h2p, h1p, h2pw, h2pb, h2tw, h2tb, out, N);
}

// round 5
// speedup vs baseline: 4.4198x; 2.2180x over previous
#include <cuda_runtime.h>
#include <math.h>

#define Dn   64
#define Rn   4
#define NMAX 100000
#define EMAX 1200000
#define SEGS (NMAX * Rn)
#define BSTR 72           // weight smem stride in words: 72 % 32 == 8 -> conflict-free B frags

// ---------------- scratch ----------------
__device__ int   g_deg[SEGS];
__device__ int   g_off[SEGS + 1];
__device__ int   g_cur[SEGS];
__device__ int   g_srcs[EMAX];
__device__ int   g_part[512];
__device__ float g_S[(size_t)SEGS * Dn];     // per-(node,rel) MEAN features
__device__ float g_h1[(size_t)NMAX * Dn];
__device__ float g_g1[(size_t)NMAX * Dn];
__device__ float g_h2[(size_t)NMAX * Dn];

__device__ __forceinline__ float sigmoidf_(float v) {
    return 1.0f / (1.0f + __expf(-v));
}

__device__ __forceinline__ unsigned f2tf32(float f) {
    unsigned u;
    asm("cvt.rna.tf32.f32 %0, %1;" : "=r"(u) : "f"(f));
    return u;
}

__device__ __forceinline__ void mma_tf32(float d[4], const unsigned a[4], const unsigned b[2]) {
    asm volatile("mma.sync.aligned.m16n8k8.row.col.f32.tf32.tf32.f32 "
                 "{%0,%1,%2,%3}, {%4,%5,%6,%7}, {%8,%9}, {%0,%1,%2,%3};"
                 : "+f"(d[0]), "+f"(d[1]), "+f"(d[2]), "+f"(d[3])
                 : "r"(a[0]), "r"(a[1]), "r"(a[2]), "r"(a[3]), "r"(b[0]), "r"(b[1]));
}

// ---------------- CSR build ----------------
__global__ void zero_deg_kernel() {
    int i = blockIdx.x * blockDim.x + threadIdx.x;
    if (i < SEGS) g_deg[i] = 0;
}

__global__ void hist_kernel(const int* __restrict__ dst, const int* __restrict__ rel, int E) {
    int e = blockIdx.x * blockDim.x + threadIdx.x;
    if (e < E) atomicAdd(&g_deg[dst[e] * Rn + rel[e]], 1);
}

__global__ void __launch_bounds__(1024) scan1_kernel(int n) {
    __shared__ int wsum[32];
    int i = blockIdx.x * 1024 + threadIdx.x;
    int lane = threadIdx.x & 31, wid = threadIdx.x >> 5;
    int v = (i < n) ? g_deg[i] : 0;
    int s = v;
#pragma unroll
    for (int d = 1; d < 32; d <<= 1) {
        int t = __shfl_up_sync(0xffffffffu, s, d);
        if (lane >= d) s += t;
    }
    if (lane == 31) wsum[wid] = s;
    __syncthreads();
    if (wid == 0) {
        int t = wsum[lane];
#pragma unroll
        for (int d = 1; d < 32; d <<= 1) {
            int u = __shfl_up_sync(0xffffffffu, t, d);
            if (lane >= d) t += u;
        }
        wsum[lane] = t;
    }
    __syncthreads();
    int add = (wid > 0) ? wsum[wid - 1] : 0;
    int inc = s + add;
    if (i < n) g_off[i] = inc - v;
    if (threadIdx.x == 1023) g_part[blockIdx.x] = inc;
}

__global__ void __launch_bounds__(512) scan2_kernel(int n) {
    __shared__ int wsum[16];
    int i = threadIdx.x;
    int lane = i & 31, wid = i >> 5;
    int v = (i < n) ? g_part[i] : 0;
    int s = v;
#pragma unroll
    for (int d = 1; d < 32; d <<= 1) {
        int t = __shfl_up_sync(0xffffffffu, s, d);
        if (lane >= d) s += t;
    }
    if (lane == 31) wsum[wid] = s;
    __syncthreads();
    if (wid == 0 && lane < 16) {
        int t = wsum[lane];
#pragma unroll
        for (int d = 1; d < 16; d <<= 1) {
            int u = __shfl_up_sync(0x0000ffffu, t, d);
            if (lane >= d) t += u;
        }
        wsum[lane] = t;
    }
    __syncthreads();
    int add = (wid > 0) ? wsum[wid - 1] : 0;
    if (i < n) g_part[i] = s - v + add;
}

__global__ void scan3_kernel(int n, int E) {
    int i = blockIdx.x * blockDim.x + threadIdx.x;
    if (i < n) {
        int o = g_off[i] + g_part[i >> 10];
        g_off[i] = o;
        g_cur[i] = o;
    }
    if (i == 0) g_off[n] = E;
}

__global__ void scatter_kernel(const int* __restrict__ src, const int* __restrict__ dst,
                               const int* __restrict__ rel, int E) {
    int e = blockIdx.x * blockDim.x + threadIdx.x;
    if (e >= E) return;
    int seg = dst[e] * Rn + rel[e];
    int p = atomicAdd(&g_cur[seg], 1);
    g_srcs[p] = src[e];
}

// ---------------- aggregate: S[seg] = MEAN over edges of x[src] ----------------
__global__ void __launch_bounds__(256) aggregate_kernel(const float* __restrict__ x) {
    int t = blockIdx.x * 256 + threadIdx.x;
    int seg = t >> 4;
    int lane = t & 15;
    if (seg >= SEGS) return;
    int e0 = __ldg(&g_off[seg]);
    int e1 = __ldg(&g_off[seg + 1]);
    float4 acc = make_float4(0.f, 0.f, 0.f, 0.f);
    for (int e = e0; e < e1; e++) {
        int s = __ldg(&g_srcs[e]);
        float4 v = *reinterpret_cast<const float4*>(x + (size_t)s * Dn + lane * 4);
        acc.x += v.x; acc.y += v.y; acc.z += v.z; acc.w += v.w;
    }
    int d = e1 - e0;
    float inv = 1.0f / (float)(d > 1 ? d : 1);
    acc.x *= inv; acc.y *= inv; acc.z *= inv; acc.w *= inv;
    *reinterpret_cast<float4*>(g_S + (size_t)seg * Dn + lane * 4) = acc;
}

// ---------------- conv via tf32 mma: out = sigmoid([S_mean | x] @ W^T + b) ----------------
// 256 threads / 8 warps, 32 nodes per warp -> 256 nodes per block.
__global__ void __launch_bounds__(256)
conv_mma_kernel(const float* __restrict__ xin,
                const float* __restrict__ S,
                const float* __restrict__ w,   // [64][256]
                const float* __restrict__ b,
                const float* __restrict__ ws,  // [64][64]
                const float* __restrict__ bs,
                float* __restrict__ out,
                int N) {
    extern __shared__ unsigned smu[];
    unsigned* sw = smu;                           // 320 * BSTR words
    float* sb = (float*)(smu + 320 * BSTR);       // 64
    int tid = threadIdx.x;

    for (int idx = tid; idx < Dn * 256; idx += 256) {
        int j = idx >> 8, k = idx & 255;
        sw[k * BSTR + j] = f2tf32(w[idx]);
    }
    for (int idx = tid; idx < Dn * Dn; idx += 256) {
        int j = idx >> 6, k = idx & 63;
        sw[(256 + k) * BSTR + j] = f2tf32(ws[idx]);
    }
    if (tid < Dn) sb[tid] = b[tid] + bs[tid];
    __syncthreads();

    int lane = tid & 31, warp = tid >> 5;
    int g = lane >> 2, q = lane & 3;
    int mbase = blockIdx.x * 256 + warp * 32;

    int r0 = mbase + g, r1 = r0 + 8, r2 = r0 + 16, r3 = r0 + 24;
    int cr0 = min(r0, N - 1), cr1 = min(r1, N - 1);
    int cr2 = min(r2, N - 1), cr3 = min(r3, N - 1);

    float acc[2][8][4];
#pragma unroll
    for (int mt = 0; mt < 2; mt++)
#pragma unroll
        for (int n = 0; n < 8; n++)
#pragma unroll
            for (int i = 0; i < 4; i++) acc[mt][n][i] = 0.f;

    const float* S0 = S + (size_t)cr0 * 256;
    const float* S1 = S + (size_t)cr1 * 256;
    const float* S2 = S + (size_t)cr2 * 256;
    const float* S3 = S + (size_t)cr3 * 256;

#pragma unroll 4
    for (int ks = 0; ks < 32; ks++) {
        int k0 = ks * 8;
        unsigned a0[4], a1[4];
        a0[0] = f2tf32(S0[k0 + q]);     a0[1] = f2tf32(S1[k0 + q]);
        a0[2] = f2tf32(S0[k0 + q + 4]); a0[3] = f2tf32(S1[k0 + q + 4]);
        a1[0] = f2tf32(S2[k0 + q]);     a1[1] = f2tf32(S3[k0 + q]);
        a1[2] = f2tf32(S2[k0 + q + 4]); a1[3] = f2tf32(S3[k0 + q + 4]);
        const unsigned* w0 = sw + (k0 + q) * BSTR + g;
        const unsigned* w1 = w0 + 4 * BSTR;
#pragma unroll
        for (int n = 0; n < 8; n++) {
            unsigned bb[2] = { w0[n * 8], w1[n * 8] };
            mma_tf32(acc[0][n], a0, bb);
            mma_tf32(acc[1][n], a1, bb);
        }
    }

    const float* X0 = xin + (size_t)cr0 * Dn;
    const float* X1 = xin + (size_t)cr1 * Dn;
    const float* X2 = xin + (size_t)cr2 * Dn;
    const float* X3 = xin + (size_t)cr3 * Dn;
#pragma unroll
    for (int ks = 0; ks < 8; ks++) {
        int k0 = ks * 8;
        unsigned a0[4], a1[4];
        a0[0] = f2tf32(X0[k0 + q]);     a0[1] = f2tf32(X1[k0 + q]);
        a0[2] = f2tf32(X0[k0 + q + 4]); a0[3] = f2tf32(X1[k0 + q + 4]);
        a1[0] = f2tf32(X2[k0 + q]);     a1[1] = f2tf32(X3[k0 + q]);
        a1[2] = f2tf32(X2[k0 + q + 4]); a1[3] = f2tf32(X3[k0 + q + 4]);
        const unsigned* w0 = sw + (256 + k0 + q) * BSTR + g;
        const unsigned* w1 = w0 + 4 * BSTR;
#pragma unroll
        for (int n = 0; n < 8; n++) {
            unsigned bb[2] = { w0[n * 8], w1[n * 8] };
            mma_tf32(acc[0][n], a0, bb);
            mma_tf32(acc[1][n], a1, bb);
        }
    }

#pragma unroll
    for (int n = 0; n < 8; n++) {
        int col = n * 8 + 2 * q;
        float b0v = sb[col], b1v = sb[col + 1];
        if (r0 < N) {
            float2 o = { sigmoidf_(acc[0][n][0] + b0v), sigmoidf_(acc[0][n][1] + b1v) };
            *reinterpret_cast<float2*>(out + (size_t)r0 * Dn + col) = o;
        }
        if (r1 < N) {
            float2 o = { sigmoidf_(acc[0][n][2] + b0v), sigmoidf_(acc[0][n][3] + b1v) };
            *reinterpret_cast<float2*>(out + (size_t)r1 * Dn + col) = o;
        }
        if (r2 < N) {
            float2 o = { sigmoidf_(acc[1][n][0] + b0v), sigmoidf_(acc[1][n][1] + b1v) };
            *reinterpret_cast<float2*>(out + (size_t)r2 * Dn + col) = o;
        }
        if (r3 < N) {
            float2 o = { sigmoidf_(acc[1][n][2] + b0v), sigmoidf_(acc[1][n][3] + b1v) };
            *reinterpret_cast<float2*>(out + (size_t)r3 * Dn + col) = o;
        }
    }
}

// ---------------- highway via tf32 mma ----------------
// 256 threads / 8 warps, 16 nodes per warp -> 128 nodes per block.
__global__ void __launch_bounds__(256)
highway_mma_kernel(const float* __restrict__ h,
                   const float* __restrict__ prev,
                   const float* __restrict__ pw,   // [64][128]
                   const float* __restrict__ pb,
                   const float* __restrict__ tw,   // [64][128]
                   const float* __restrict__ tb,
                   float* __restrict__ out,
                   int N) {
    extern __shared__ unsigned smu[];
    unsigned* sp = smu;                            // 128 * BSTR
    unsigned* st = sp + 128 * BSTR;                // 128 * BSTR
    float* sbp = (float*)(st + 128 * BSTR);        // 64
    float* sbt = sbp + Dn;                         // 64
    int tid = threadIdx.x;

    for (int idx = tid; idx < Dn * 128; idx += 256) {
        int j = idx >> 7, k = idx & 127;
        sp[k * BSTR + j] = f2tf32(pw[idx]);
        st[k * BSTR + j] = f2tf32(tw[idx]);
    }
    if (tid < Dn) { sbp[tid] = pb[tid]; sbt[tid] = tb[tid]; }
    __syncthreads();

    int lane = tid & 31, warp = tid >> 5;
    int g = lane >> 2, q = lane & 3;
    int mbase = blockIdx.x * 128 + warp * 16;

    int r0 = mbase + g, r1 = r0 + 8;
    int cr0 = min(r0, N - 1), cr1 = min(r1, N - 1);

    float accP[8][4], accT[8][4];
#pragma unroll
    for (int n = 0; n < 8; n++)
#pragma unroll
        for (int i = 0; i < 4; i++) { accP[n][i] = 0.f; accT[n][i] = 0.f; }

    const float* H0 = h + (size_t)cr0 * Dn;
    const float* H1 = h + (size_t)cr1 * Dn;
    const float* P0 = prev + (size_t)cr0 * Dn;
    const float* P1 = prev + (size_t)cr1 * Dn;

#pragma unroll
    for (int ks = 0; ks < 8; ks++) {
        int k0 = ks * 8;
        unsigned a[4];
        a[0] = f2tf32(H0[k0 + q]);     a[1] = f2tf32(H1[k0 + q]);
        a[2] = f2tf32(H0[k0 + q + 4]); a[3] = f2tf32(H1[k0 + q + 4]);
        const unsigned* p0 = sp + (k0 + q) * BSTR + g;
        const unsigned* p1 = p0 + 4 * BSTR;
        const unsigned* t0 = st + (k0 + q) * BSTR + g;
        const unsigned* t1 = t0 + 4 * BSTR;
#pragma unroll
        for (int n = 0; n < 8; n++) {
            unsigned bp[2] = { p0[n * 8], p1[n * 8] };
            unsigned bt[2] = { t0[n * 8], t1[n * 8] };
            mma_tf32(accP[n], a, bp);
            mma_tf32(accT[n], a, bt);
        }
    }
#pragma unroll
    for (int ks = 0; ks < 8; ks++) {
        int k0 = ks * 8;
        unsigned a[4];
        a[0] = f2tf32(P0[k0 + q]);     a[1] = f2tf32(P1[k0 + q]);
        a[2] = f2tf32(P0[k0 + q + 4]); a[3] = f2tf32(P1[k0 + q + 4]);
        const unsigned* p0 = sp + (64 + k0 + q) * BSTR + g;
        const unsigned* p1 = p0 + 4 * BSTR;
        const unsigned* t0 = st + (64 + k0 + q) * BSTR + g;
        const unsigned* t1 = t0 + 4 * BSTR;
#pragma unroll
        for (int n = 0; n < 8; n++) {
            unsigned bp[2] = { p0[n * 8], p1[n * 8] };
            unsigned bt[2] = { t0[n * 8], t1[n * 8] };
            mma_tf32(accP[n], a, bp);
            mma_tf32(accT[n], a, bt);
        }
    }

#pragma unroll
    for (int n = 0; n < 8; n++) {
        int col = n * 8 + 2 * q;
        float bp0 = sbp[col], bp1 = sbp[col + 1];
        float bt0 = sbt[col], bt1 = sbt[col + 1];
        if (r0 < N) {
            float2 hv = *reinterpret_cast<const float2*>(h + (size_t)r0 * Dn + col);
            float pr0 = fmaxf(accP[n][0] + bp0, 0.f);
            float pr1 = fmaxf(accP[n][1] + bp1, 0.f);
            float g0 = sigmoidf_(accT[n][0] + bt0);
            float g1 = sigmoidf_(accT[n][1] + bt1);
            float2 o = { g0 * pr0 + (1.f - g0) * hv.x, g1 * pr1 + (1.f - g1) * hv.y };
            *reinterpret_cast<float2*>(out + (size_t)r0 * Dn + col) = o;
        }
        if (r1 < N) {
            float2 hv = *reinterpret_cast<const float2*>(h + (size_t)r1 * Dn + col);
            float pr0 = fmaxf(accP[n][2] + bp0, 0.f);
            float pr1 = fmaxf(accP[n][3] + bp1, 0.f);
            float g0 = sigmoidf_(accT[n][2] + bt0);
            float g1 = sigmoidf_(accT[n][3] + bt1);
            float2 o = { g0 * pr0 + (1.f - g0) * hv.x, g1 * pr1 + (1.f - g1) * hv.y };
            *reinterpret_cast<float2*>(out + (size_t)r1 * Dn + col) = o;
        }
    }
}

// ---------------- launch ----------------
extern "C" void kernel_launch(void* const* d_in, const int* in_sizes, int n_in,
                              void* d_out, int out_size) {
    const float* x    = (const float*)d_in[0];
    const int*   src  = (const int*)d_in[1];
    const int*   dst  = (const int*)d_in[2];
    const int*   rel  = (const int*)d_in[3];
    const float* c1w  = (const float*)d_in[4];
    const float* c1b  = (const float*)d_in[5];
    const float* c1ws = (const float*)d_in[6];
    const float* c1bs = (const float*)d_in[7];
    const float* h1pw = (const float*)d_in[8];
    const float* h1pb = (const float*)d_in[9];
    const float* h1tw = (const float*)d_in[10];
    const float* h1tb = (const float*)d_in[11];
    const float* c2w  = (const float*)d_in[12];
    const float* c2b  = (const float*)d_in[13];
    const float* c2ws = (const float*)d_in[14];
    const float* c2bs = (const float*)d_in[15];
    const float* h2pw = (const float*)d_in[16];
    const float* h2pb = (const float*)d_in[17];
    const float* h2tw = (const float*)d_in[18];
    const float* h2tb = (const float*)d_in[19];
    float* out = (float*)d_out;

    int N = in_sizes[0] / Dn;
    int E = in_sizes[1];

    float *Sp, *h1p, *g1p, *h2p;
    cudaGetSymbolAddress((void**)&Sp, g_S);
    cudaGetSymbolAddress((void**)&h1p, g_h1);
    cudaGetSymbolAddress((void**)&g1p, g_g1);
    cudaGetSymbolAddress((void**)&h2p, g_h2);

    const int convSmem = 320 * BSTR * 4 + 64 * 4;
    const int hwSmem   = 2 * 128 * BSTR * 4 + 128 * 4;
    cudaFuncSetAttribute(conv_mma_kernel, cudaFuncAttributeMaxDynamicSharedMemorySize, convSmem);
    cudaFuncSetAttribute(highway_mma_kernel, cudaFuncAttributeMaxDynamicSharedMemorySize, hwSmem);

    int convGrid = (N + 255) / 256;
    int hwGrid   = (N + 127) / 128;
    int scanBlocks = (SEGS + 1023) / 1024;

    // ---- CSR build (graph identical in both layers) ----
    zero_deg_kernel<<<(SEGS + 255) / 256, 256>>>();
    hist_kernel<<<(E + 255) / 256, 256>>>(dst, rel, E);
    scan1_kernel<<<scanBlocks, 1024>>>(SEGS);
    scan2_kernel<<<1, 512>>>(scanBlocks);
    scan3_kernel<<<(SEGS + 255) / 256, 256>>>(SEGS, E);
    scatter_kernel<<<(E + 255) / 256, 256>>>(src, dst, rel, E);

    int aggGrid = SEGS / 16;

    // ---- layer 1 ----
    aggregate_kernel<<<aggGrid, 256>>>(x);
    conv_mma_kernel<<<convGrid, 256, convSmem>>>(x, Sp, c1w, c1b, c1ws, c1bs, h1p, N);
    highway_mma_kernel<<<hwGrid, 256, hwSmem>>>(h1p, x, h1pw, h1pb, h1tw, h1tb, g1p, N);

    // ---- layer 2 ----
    aggregate_kernel<<<aggGrid, 256>>>(g1p);
    conv_mma_kernel<<<convGrid, 256, convSmem>>>(g1p, Sp, c2w, c2b, c2ws, c2bs, h2p, N);
    highway_mma_kernel<<<hwGrid, 256, hwSmem>>>(h2p, h1p, h2pw, h2pb, h2tw, h2tb, out, N);
}

// round 6
// speedup vs baseline: 4.9913x; 1.1293x over previous
#include <cuda_runtime.h>
#include <math.h>

#define Dn   64
#define Rn   4
#define NMAX 100000
#define EMAX 1200000
#define SEGS (NMAX * Rn)
#define BSTR 68   // weight smem stride: banks (2q*68)%32 = 8q -> conflict-free permuted B frags

// ---------------- scratch ----------------
__device__ int   g_deg[SEGS];
__device__ int   g_off[SEGS + 1];
__device__ int   g_cur[SEGS];
__device__ int   g_srcs[EMAX];
__device__ int   g_part[512];
__device__ float g_S[(size_t)SEGS * Dn];     // per-(node,rel) MEAN features
__device__ float g_h1[(size_t)NMAX * Dn];
__device__ float g_g1[(size_t)NMAX * Dn];
__device__ float g_h2[(size_t)NMAX * Dn];

__device__ __forceinline__ float sigmoidf_(float v) {
    return 1.0f / (1.0f + __expf(-v));
}

__device__ __forceinline__ unsigned f2tf32(float f) {
    unsigned u;
    asm("cvt.rna.tf32.f32 %0, %1;" : "=r"(u) : "f"(f));
    return u;
}

__device__ __forceinline__ void mma_tf32(float d[4], const unsigned a[4], const unsigned b[2]) {
    asm volatile("mma.sync.aligned.m16n8k8.row.col.f32.tf32.tf32.f32 "
                 "{%0,%1,%2,%3}, {%4,%5,%6,%7}, {%8,%9}, {%0,%1,%2,%3};"
                 : "+f"(d[0]), "+f"(d[1]), "+f"(d[2]), "+f"(d[3])
                 : "r"(a[0]), "r"(a[1]), "r"(a[2]), "r"(a[3]), "r"(b[0]), "r"(b[1]));
}

// ---------------- CSR build ----------------
__global__ void zero_deg_kernel() {
    int i = blockIdx.x * blockDim.x + threadIdx.x;
    if (i < SEGS) g_deg[i] = 0;
}

__global__ void hist_kernel(const int* __restrict__ dst, const int* __restrict__ rel, int E) {
    int e = blockIdx.x * blockDim.x + threadIdx.x;
    if (e < E) atomicAdd(&g_deg[dst[e] * Rn + rel[e]], 1);
}

__global__ void __launch_bounds__(1024) scan1_kernel(int n) {
    __shared__ int wsum[32];
    int i = blockIdx.x * 1024 + threadIdx.x;
    int lane = threadIdx.x & 31, wid = threadIdx.x >> 5;
    int v = (i < n) ? g_deg[i] : 0;
    int s = v;
#pragma unroll
    for (int d = 1; d < 32; d <<= 1) {
        int t = __shfl_up_sync(0xffffffffu, s, d);
        if (lane >= d) s += t;
    }
    if (lane == 31) wsum[wid] = s;
    __syncthreads();
    if (wid == 0) {
        int t = wsum[lane];
#pragma unroll
        for (int d = 1; d < 32; d <<= 1) {
            int u = __shfl_up_sync(0xffffffffu, t, d);
            if (lane >= d) t += u;
        }
        wsum[lane] = t;
    }
    __syncthreads();
    int add = (wid > 0) ? wsum[wid - 1] : 0;
    int inc = s + add;
    if (i < n) g_off[i] = inc - v;
    if (threadIdx.x == 1023) g_part[blockIdx.x] = inc;
}

__global__ void __launch_bounds__(512) scan2_kernel(int n) {
    __shared__ int wsum[16];
    int i = threadIdx.x;
    int lane = i & 31, wid = i >> 5;
    int v = (i < n) ? g_part[i] : 0;
    int s = v;
#pragma unroll
    for (int d = 1; d < 32; d <<= 1) {
        int t = __shfl_up_sync(0xffffffffu, s, d);
        if (lane >= d) s += t;
    }
    if (lane == 31) wsum[wid] = s;
    __syncthreads();
    if (wid == 0 && lane < 16) {
        int t = wsum[lane];
#pragma unroll
        for (int d = 1; d < 16; d <<= 1) {
            int u = __shfl_up_sync(0x0000ffffu, t, d);
            if (lane >= d) t += u;
        }
        wsum[lane] = t;
    }
    __syncthreads();
    int add = (wid > 0) ? wsum[wid - 1] : 0;
    if (i < n) g_part[i] = s - v + add;
}

__global__ void scan3_kernel(int n, int E) {
    int i = blockIdx.x * blockDim.x + threadIdx.x;
    if (i < n) {
        int o = g_off[i] + g_part[i >> 10];
        g_off[i] = o;
        g_cur[i] = o;
    }
    if (i == 0) g_off[n] = E;
}

__global__ void scatter_kernel(const int* __restrict__ src, const int* __restrict__ dst,
                               const int* __restrict__ rel, int E) {
    int e = blockIdx.x * blockDim.x + threadIdx.x;
    if (e >= E) return;
    int seg = dst[e] * Rn + rel[e];
    int p = atomicAdd(&g_cur[seg], 1);
    g_srcs[p] = src[e];
}

// ---------------- aggregate: S[seg] = MEAN over edges of x[src] ----------------
__global__ void __launch_bounds__(256) aggregate_kernel(const float* __restrict__ x) {
    int t = blockIdx.x * 256 + threadIdx.x;
    int seg = t >> 4;
    int lane = t & 15;
    if (seg >= SEGS) return;
    int e0 = __ldg(&g_off[seg]);
    int e1 = __ldg(&g_off[seg + 1]);
    float4 acc = make_float4(0.f, 0.f, 0.f, 0.f);
    int e = e0;
    for (; e + 1 < e1; e += 2) {
        int s0 = __ldg(&g_srcs[e]);
        int s1 = __ldg(&g_srcs[e + 1]);
        float4 v0 = *reinterpret_cast<const float4*>(x + (size_t)s0 * Dn + lane * 4);
        float4 v1 = *reinterpret_cast<const float4*>(x + (size_t)s1 * Dn + lane * 4);
        acc.x += v0.x + v1.x; acc.y += v0.y + v1.y;
        acc.z += v0.z + v1.z; acc.w += v0.w + v1.w;
    }
    if (e < e1) {
        int s0 = __ldg(&g_srcs[e]);
        float4 v0 = *reinterpret_cast<const float4*>(x + (size_t)s0 * Dn + lane * 4);
        acc.x += v0.x; acc.y += v0.y; acc.z += v0.z; acc.w += v0.w;
    }
    int d = e1 - e0;
    float inv = 1.0f / (float)(d > 1 ? d : 1);
    acc.x *= inv; acc.y *= inv; acc.z *= inv; acc.w *= inv;
    *reinterpret_cast<float4*>(g_S + (size_t)seg * Dn + lane * 4) = acc;
}

// ---------------- conv via tf32 mma: out = sigmoid([S_mean | x] @ W^T + b) ----------------
// 256 threads / 8 warps, 32 nodes per warp -> 256 nodes per block.
// Permuted-k frags: logical q <-> actual k0+2q, logical q+4 <-> actual k0+2q+1.
__global__ void __launch_bounds__(256)
conv_mma_kernel(const float* __restrict__ xin,
                const float* __restrict__ S,
                const float* __restrict__ w,   // [64][256]
                const float* __restrict__ b,
                const float* __restrict__ ws,  // [64][64]
                const float* __restrict__ bs,
                float* __restrict__ out,
                int N) {
    extern __shared__ unsigned smu[];
    unsigned* sw = smu;                           // 320 * BSTR words
    float* sb = (float*)(smu + 320 * BSTR);       // 64
    int tid = threadIdx.x;

    for (int idx = tid; idx < Dn * 256; idx += 256) {
        int j = idx >> 8, k = idx & 255;
        sw[k * BSTR + j] = f2tf32(w[idx]);
    }
    for (int idx = tid; idx < Dn * Dn; idx += 256) {
        int j = idx >> 6, k = idx & 63;
        sw[(256 + k) * BSTR + j] = f2tf32(ws[idx]);
    }
    if (tid < Dn) sb[tid] = b[tid] + bs[tid];
    __syncthreads();

    int lane = tid & 31, warp = tid >> 5;
    int g = lane >> 2, q = lane & 3;
    int mbase = blockIdx.x * 256 + warp * 32;

    int r0 = mbase + g, r1 = r0 + 8, r2 = r0 + 16, r3 = r0 + 24;
    int cr0 = min(r0, N - 1), cr1 = min(r1, N - 1);
    int cr2 = min(r2, N - 1), cr3 = min(r3, N - 1);

    float acc[2][8][4];
#pragma unroll
    for (int mt = 0; mt < 2; mt++)
#pragma unroll
        for (int n = 0; n < 8; n++)
#pragma unroll
            for (int i = 0; i < 4; i++) acc[mt][n][i] = 0.f;

    const float* S0 = S + (size_t)cr0 * 256;
    const float* S1 = S + (size_t)cr1 * 256;
    const float* S2 = S + (size_t)cr2 * 256;
    const float* S3 = S + (size_t)cr3 * 256;

#pragma unroll 4
    for (int ks = 0; ks < 32; ks++) {
        int ka = ks * 8 + 2 * q;
        float2 s0 = *reinterpret_cast<const float2*>(S0 + ka);
        float2 s1 = *reinterpret_cast<const float2*>(S1 + ka);
        float2 s2 = *reinterpret_cast<const float2*>(S2 + ka);
        float2 s3 = *reinterpret_cast<const float2*>(S3 + ka);
        unsigned a0[4] = { f2tf32(s0.x), f2tf32(s1.x), f2tf32(s0.y), f2tf32(s1.y) };
        unsigned a1[4] = { f2tf32(s2.x), f2tf32(s3.x), f2tf32(s2.y), f2tf32(s3.y) };
        const unsigned* w0 = sw + ka * BSTR + g;
#pragma unroll
        for (int n = 0; n < 8; n++) {
            unsigned bb[2] = { w0[n * 8], w0[BSTR + n * 8] };
            mma_tf32(acc[0][n], a0, bb);
            mma_tf32(acc[1][n], a1, bb);
        }
    }

    const float* X0 = xin + (size_t)cr0 * Dn;
    const float* X1 = xin + (size_t)cr1 * Dn;
    const float* X2 = xin + (size_t)cr2 * Dn;
    const float* X3 = xin + (size_t)cr3 * Dn;
#pragma unroll
    for (int ks = 0; ks < 8; ks++) {
        int ka = ks * 8 + 2 * q;
        float2 s0 = *reinterpret_cast<const float2*>(X0 + ka);
        float2 s1 = *reinterpret_cast<const float2*>(X1 + ka);
        float2 s2 = *reinterpret_cast<const float2*>(X2 + ka);
        float2 s3 = *reinterpret_cast<const float2*>(X3 + ka);
        unsigned a0[4] = { f2tf32(s0.x), f2tf32(s1.x), f2tf32(s0.y), f2tf32(s1.y) };
        unsigned a1[4] = { f2tf32(s2.x), f2tf32(s3.x), f2tf32(s2.y), f2tf32(s3.y) };
        const unsigned* w0 = sw + (256 + ka) * BSTR + g;
#pragma unroll
        for (int n = 0; n < 8; n++) {
            unsigned bb[2] = { w0[n * 8], w0[BSTR + n * 8] };
            mma_tf32(acc[0][n], a0, bb);
            mma_tf32(acc[1][n], a1, bb);
        }
    }

#pragma unroll
    for (int n = 0; n < 8; n++) {
        int col = n * 8 + 2 * q;
        float b0v = sb[col], b1v = sb[col + 1];
        if (r0 < N) {
            float2 o = { sigmoidf_(acc[0][n][0] + b0v), sigmoidf_(acc[0][n][1] + b1v) };
            *reinterpret_cast<float2*>(out + (size_t)r0 * Dn + col) = o;
        }
        if (r1 < N) {
            float2 o = { sigmoidf_(acc[0][n][2] + b0v), sigmoidf_(acc[0][n][3] + b1v) };
            *reinterpret_cast<float2*>(out + (size_t)r1 * Dn + col) = o;
        }
        if (r2 < N) {
            float2 o = { sigmoidf_(acc[1][n][0] + b0v), sigmoidf_(acc[1][n][1] + b1v) };
            *reinterpret_cast<float2*>(out + (size_t)r2 * Dn + col) = o;
        }
        if (r3 < N) {
            float2 o = { sigmoidf_(acc[1][n][2] + b0v), sigmoidf_(acc[1][n][3] + b1v) };
            *reinterpret_cast<float2*>(out + (size_t)r3 * Dn + col) = o;
        }
    }
}

// ---------------- highway via tf32 mma ----------------
// 256 threads / 8 warps, 16 nodes per warp -> 128 nodes per block.
__global__ void __launch_bounds__(256)
highway_mma_kernel(const float* __restrict__ h,
                   const float* __restrict__ prev,
                   const float* __restrict__ pw,   // [64][128]
                   const float* __restrict__ pb,
                   const float* __restrict__ tw,   // [64][128]
                   const float* __restrict__ tb,
                   float* __restrict__ out,
                   int N) {
    extern __shared__ unsigned smu[];
    unsigned* sp = smu;                            // 128 * BSTR
    unsigned* st = sp + 128 * BSTR;                // 128 * BSTR
    float* sbp = (float*)(st + 128 * BSTR);        // 64
    float* sbt = sbp + Dn;                         // 64
    int tid = threadIdx.x;

    for (int idx = tid; idx < Dn * 128; idx += 256) {
        int j = idx >> 7, k = idx & 127;
        sp[k * BSTR + j] = f2tf32(pw[idx]);
        st[k * BSTR + j] = f2tf32(tw[idx]);
    }
    if (tid < Dn) { sbp[tid] = pb[tid]; sbt[tid] = tb[tid]; }
    __syncthreads();

    int lane = tid & 31, warp = tid >> 5;
    int g = lane >> 2, q = lane & 3;
    int mbase = blockIdx.x * 128 + warp * 16;

    int r0 = mbase + g, r1 = r0 + 8;
    int cr0 = min(r0, N - 1), cr1 = min(r1, N - 1);

    float accP[8][4], accT[8][4];
#pragma unroll
    for (int n = 0; n < 8; n++)
#pragma unroll
        for (int i = 0; i < 4; i++) { accP[n][i] = 0.f; accT[n][i] = 0.f; }

    const float* H0 = h + (size_t)cr0 * Dn;
    const float* H1 = h + (size_t)cr1 * Dn;
    const float* P0 = prev + (size_t)cr0 * Dn;
    const float* P1 = prev + (size_t)cr1 * Dn;

#pragma unroll
    for (int ks = 0; ks < 8; ks++) {
        int ka = ks * 8 + 2 * q;
        float2 s0 = *reinterpret_cast<const float2*>(H0 + ka);
        float2 s1 = *reinterpret_cast<const float2*>(H1 + ka);
        unsigned a[4] = { f2tf32(s0.x), f2tf32(s1.x), f2tf32(s0.y), f2tf32(s1.y) };
        const unsigned* p0 = sp + ka * BSTR + g;
        const unsigned* t0 = st + ka * BSTR + g;
#pragma unroll
        for (int n = 0; n < 8; n++) {
            unsigned bp[2] = { p0[n * 8], p0[BSTR + n * 8] };
            unsigned bt[2] = { t0[n * 8], t0[BSTR + n * 8] };
            mma_tf32(accP[n], a, bp);
            mma_tf32(accT[n], a, bt);
        }
    }
#pragma unroll
    for (int ks = 0; ks < 8; ks++) {
        int ka = ks * 8 + 2 * q;
        float2 s0 = *reinterpret_cast<const float2*>(P0 + ka);
        float2 s1 = *reinterpret_cast<const float2*>(P1 + ka);
        unsigned a[4] = { f2tf32(s0.x), f2tf32(s1.x), f2tf32(s0.y), f2tf32(s1.y) };
        const unsigned* p0 = sp + (64 + ka) * BSTR + g;
        const unsigned* t0 = st + (64 + ka) * BSTR + g;
#pragma unroll
        for (int n = 0; n < 8; n++) {
            unsigned bp[2] = { p0[n * 8], p0[BSTR + n * 8] };
            unsigned bt[2] = { t0[n * 8], t0[BSTR + n * 8] };
            mma_tf32(accP[n], a, bp);
            mma_tf32(accT[n], a, bt);
        }
    }

#pragma unroll
    for (int n = 0; n < 8; n++) {
        int col = n * 8 + 2 * q;
        float bp0 = sbp[col], bp1 = sbp[col + 1];
        float bt0 = sbt[col], bt1 = sbt[col + 1];
        if (r0 < N) {
            float2 hv = *reinterpret_cast<const float2*>(h + (size_t)r0 * Dn + col);
            float pr0 = fmaxf(accP[n][0] + bp0, 0.f);
            float pr1 = fmaxf(accP[n][1] + bp1, 0.f);
            float g0 = sigmoidf_(accT[n][0] + bt0);
            float g1 = sigmoidf_(accT[n][1] + bt1);
            float2 o = { g0 * pr0 + (1.f - g0) * hv.x, g1 * pr1 + (1.f - g1) * hv.y };
            *reinterpret_cast<float2*>(out + (size_t)r0 * Dn + col) = o;
        }
        if (r1 < N) {
            float2 hv = *reinterpret_cast<const float2*>(h + (size_t)r1 * Dn + col);
            float pr0 = fmaxf(accP[n][2] + bp0, 0.f);
            float pr1 = fmaxf(accP[n][3] + bp1, 0.f);
            float g0 = sigmoidf_(accT[n][2] + bt0);
            float g1 = sigmoidf_(accT[n][3] + bt1);
            float2 o = { g0 * pr0 + (1.f - g0) * hv.x, g1 * pr1 + (1.f - g1) * hv.y };
            *reinterpret_cast<float2*>(out + (size_t)r1 * Dn + col) = o;
        }
    }
}

// ---------------- launch ----------------
extern "C" void kernel_launch(void* const* d_in, const int* in_sizes, int n_in,
                              void* d_out, int out_size) {
    const float* x    = (const float*)d_in[0];
    const int*   src  = (const int*)d_in[1];
    const int*   dst  = (const int*)d_in[2];
    const int*   rel  = (const int*)d_in[3];
    const float* c1w  = (const float*)d_in[4];
    const float* c1b  = (const float*)d_in[5];
    const float* c1ws = (const float*)d_in[6];
    const float* c1bs = (const float*)d_in[7];
    const float* h1pw = (const float*)d_in[8];
    const float* h1pb = (const float*)d_in[9];
    const float* h1tw = (const float*)d_in[10];
    const float* h1tb = (const float*)d_in[11];
    const float* c2w  = (const float*)d_in[12];
    const float* c2b  = (const float*)d_in[13];
    const float* c2ws = (const float*)d_in[14];
    const float* c2bs = (const float*)d_in[15];
    const float* h2pw = (const float*)d_in[16];
    const float* h2pb = (const float*)d_in[17];
    const float* h2tw = (const float*)d_in[18];
    const float* h2tb = (const float*)d_in[19];
    float* out = (float*)d_out;

    int N = in_sizes[0] / Dn;
    int E = in_sizes[1];

    float *Sp, *h1p, *g1p, *h2p;
    cudaGetSymbolAddress((void**)&Sp, g_S);
    cudaGetSymbolAddress((void**)&h1p, g_h1);
    cudaGetSymbolAddress((void**)&g1p, g_g1);
    cudaGetSymbolAddress((void**)&h2p, g_h2);

    const int convSmem = 320 * BSTR * 4 + 64 * 4;
    const int hwSmem   = 2 * 128 * BSTR * 4 + 128 * 4;
    cudaFuncSetAttribute(conv_mma_kernel, cudaFuncAttributeMaxDynamicSharedMemorySize, convSmem);
    cudaFuncSetAttribute(highway_mma_kernel, cudaFuncAttributeMaxDynamicSharedMemorySize, hwSmem);

    int convGrid = (N + 255) / 256;
    int hwGrid   = (N + 127) / 128;
    int scanBlocks = (SEGS + 1023) / 1024;

    // ---- CSR build (graph identical in both layers) ----
    zero_deg_kernel<<<(SEGS + 255) / 256, 256>>>();
    hist_kernel<<<(E + 255) / 256, 256>>>(dst, rel, E);
    scan1_kernel<<<scanBlocks, 1024>>>(SEGS);
    scan2_kernel<<<1, 512>>>(scanBlocks);
    scan3_kernel<<<(SEGS + 255) / 256, 256>>>(SEGS, E);
    scatter_kernel<<<(E + 255) / 256, 256>>>(src, dst, rel, E);

    int aggGrid = SEGS / 16;

    // ---- layer 1 ----
    aggregate_kernel<<<aggGrid, 256>>>(x);
    conv_mma_kernel<<<convGrid, 256, convSmem>>>(x, Sp, c1w, c1b, c1ws, c1bs, h1p, N);
    highway_mma_kernel<<<hwGrid, 256, hwSmem>>>(h1p, x, h1pw, h1pb, h1tw, h1tb, g1p, N);

    // ---- layer 2 ----
    aggregate_kernel<<<aggGrid, 256>>>(g1p);
    conv_mma_kernel<<<convGrid, 256, convSmem>>>(g1p, Sp, c2w, c2b, c2ws, c2bs, h2p, N);
    highway_mma_kernel<<<hwGrid, 256, hwSmem>>>(h2p, h1p, h2pw, h2pb, h2tw, h2tb, out, N);
}